// round 6
// baseline (speedup 1.0000x reference)
#include <cuda_runtime.h>
#include <cuda_bf16.h>

#define T_DIM 64
#define B_DIM 16
#define S_DIM 256
#define D_DIM 512
#define T_TILE 4       // t-rows per logits block
#define T_AV   8       // t-rows per AV block

// scratch: h = input @ W_comb + b_comb, stored (B, T, D)
__device__ float g_h[B_DIM * T_DIM * D_DIM];

__device__ __forceinline__ float tanh_ap(float x) {
    float y;
    asm("tanh.approx.f32 %0, %1;" : "=f"(y) : "f"(x));
    return y;
}

// ---------------------------------------------------------------------------
// Kernel 1: h[b,t,:] = input[t,b,:] @ W + bias   (M=1024, N=512, K=512)
// 64x64 tile, 512 thr (16 warps/SM), 2x4 microtile, double-buffered SMEM.
// ---------------------------------------------------------------------------
__global__ __launch_bounds__(512) void gemm_kernel(
    const float* __restrict__ A,
    const float* __restrict__ W,
    const float* __restrict__ bias)
{
    __shared__ float As[2][64][33];
    __shared__ float Bs[2][32][68];

    const int tid = threadIdx.x;
    const int tx = tid & 15;          // 16 col-groups of 4
    const int ty = tid >> 4;          // 0..31, 2 rows each
    const int m0 = blockIdx.y * 64;
    const int n0 = blockIdx.x * 64;

    // A tile: 64x32 = 512 float4, 1 per thread
    const int ar = tid >> 3, ac = (tid & 7) * 4;
    // B tile: 32x64 = 512 float4, 1 per thread
    const int br = tid >> 4, bc = (tid & 15) * 4;

    float acc[2][4];
#pragma unroll
    for (int i = 0; i < 2; ++i)
#pragma unroll
        for (int j = 0; j < 4; ++j) acc[i][j] = 0.f;

    // prologue -> buffer 0
    {
        float4 a0 = *(const float4*)&A[(size_t)(m0 + ar) * D_DIM + ac];
        float4 b0 = *(const float4*)&W[(size_t)br * D_DIM + n0 + bc];
        As[0][ar][ac + 0] = a0.x; As[0][ar][ac + 1] = a0.y;
        As[0][ar][ac + 2] = a0.z; As[0][ar][ac + 3] = a0.w;
        *(float4*)&Bs[0][br][bc] = b0;
    }
    __syncthreads();

    int buf = 0;
    for (int k0 = 0; k0 < D_DIM; k0 += 32) {
        const bool has_next = (k0 + 32) < D_DIM;
        float4 a0, b0;
        if (has_next) {
            const int kn = k0 + 32;
            a0 = *(const float4*)&A[(size_t)(m0 + ar) * D_DIM + kn + ac];
            b0 = *(const float4*)&W[(size_t)(kn + br) * D_DIM + n0 + bc];
        }

#pragma unroll
        for (int k = 0; k < 32; ++k) {
            float4 b4 = *(const float4*)&Bs[buf][k][tx * 4];
            float x0 = As[buf][ty * 2 + 0][k];
            float x1 = As[buf][ty * 2 + 1][k];
            acc[0][0] += x0 * b4.x; acc[0][1] += x0 * b4.y;
            acc[0][2] += x0 * b4.z; acc[0][3] += x0 * b4.w;
            acc[1][0] += x1 * b4.x; acc[1][1] += x1 * b4.y;
            acc[1][2] += x1 * b4.z; acc[1][3] += x1 * b4.w;
        }

        if (has_next) {
            const int nb = buf ^ 1;
            As[nb][ar][ac + 0] = a0.x; As[nb][ar][ac + 1] = a0.y;
            As[nb][ar][ac + 2] = a0.z; As[nb][ar][ac + 3] = a0.w;
            *(float4*)&Bs[nb][br][bc] = b0;
        }
        __syncthreads();
        buf ^= 1;
    }

#pragma unroll
    for (int i = 0; i < 2; ++i) {
        int m = m0 + ty * 2 + i;
        int bb = m & (B_DIM - 1);
        int tt = m >> 4;
        float* dst = &g_h[((size_t)bb * T_DIM + tt) * D_DIM + n0 + tx * 4];
#pragma unroll
        for (int j = 0; j < 4; ++j)
            dst[j] = acc[i][j] + bias[n0 + tx * 4 + j];
    }
}

// ---------------------------------------------------------------------------
// Kernel 2: logits + softmax. grid=(B, T/4)=256 blocks, 512 thr, 2 CTA/SM.
// Warp w: quarter q=w&3 (128-dim slice of D), sg=w>>2 (64 s values).
// Prefetch depth 3; butterfly reduction pipelined one iteration behind tanh.
// ---------------------------------------------------------------------------
__global__ __launch_bounds__(512, 2) void logits_kernel(
    const float* __restrict__ context,   // (B,S,D)
    const float* __restrict__ v_w,       // (D)
    const float* __restrict__ v_b,       // scalar
    float* __restrict__ out_attn)        // (B*T, S) -> normalized probs
{
    __shared__ float h_s[T_TILE * D_DIM];          // 8 KB
    __shared__ float lg[4][T_TILE][S_DIM];         // 16 KB (quarter-partials)

    const int b    = blockIdx.x;
    const int t0   = blockIdx.y * T_TILE;
    const int tid  = threadIdx.x;
    const int wid  = tid >> 5;
    const int lane = tid & 31;
    const int q    = wid & 3;
    const int sg   = wid >> 2;

    {
        const float4* hp = (const float4*)(g_h + ((size_t)b * T_DIM + t0) * D_DIM);
        float4* hs4 = (float4*)h_s;
        for (int i = tid; i < T_TILE * D_DIM / 4; i += 512) hs4[i] = hp[i];
    }
    __syncthreads();

    // ---- logits ----
    {
        const int dof = q * 32 + lane;
        const float4* h4 = (const float4*)h_s;
        float4 hh[T_TILE];
#pragma unroll
        for (int t = 0; t < T_TILE; ++t)
            hh[t] = h4[t * (D_DIM / 4) + dof];
        const float4 ww = ((const float4*)v_w)[dof];

        const float4* cbase = (const float4*)(context + (size_t)b * S_DIM * D_DIM)
                              + (size_t)(sg * 64) * (D_DIM / 4) + dof;

        float4 c0 = cbase[0];
        float4 c1 = cbase[1 * (D_DIM / 4)];
        float4 c2 = cbase[2 * (D_DIM / 4)];

        float accP[T_TILE];

        for (int si = 0; si < 64; ++si) {
            int pf = si + 3 < 64 ? si + 3 : 63;
            float4 cn = cbase[(size_t)pf * (D_DIM / 4)];

            float acc[T_TILE];
#pragma unroll
            for (int t = 0; t < T_TILE; ++t) {
                float a;
                a  = ww.x * tanh_ap(hh[t].x + c0.x);
                a += ww.y * tanh_ap(hh[t].y + c0.y);
                a += ww.z * tanh_ap(hh[t].z + c0.z);
                a += ww.w * tanh_ap(hh[t].w + c0.w);
                acc[t] = a;
            }

            // reduce PREVIOUS iteration's accumulators (overlaps with this
            // iteration's MUFU block in the SASS scheduler)
            if (si > 0) {
                float r0 = accP[0] + __shfl_xor_sync(0xffffffffu, accP[0], 16);
                float r1 = accP[1] + __shfl_xor_sync(0xffffffffu, accP[1], 16);
                float r2 = accP[2] + __shfl_xor_sync(0xffffffffu, accP[2], 16);
                float r3 = accP[3] + __shfl_xor_sync(0xffffffffu, accP[3], 16);
                float m01 = (lane & 16) ? r1 : r0;
                float m23 = (lane & 16) ? r3 : r2;
                m01 += __shfl_xor_sync(0xffffffffu, m01, 8);
                m23 += __shfl_xor_sync(0xffffffffu, m23, 8);
                float qv = (lane & 8) ? m23 : m01;
                qv += __shfl_xor_sync(0xffffffffu, qv, 4);
                qv += __shfl_xor_sync(0xffffffffu, qv, 2);
                qv += __shfl_xor_sync(0xffffffffu, qv, 1);
                if ((lane & 7) == 0) {
                    int t = ((lane >> 4) & 1) + (((lane >> 3) & 1) << 1);
                    lg[q][t][sg * 64 + si - 1] = qv;
                }
            }
#pragma unroll
            for (int t = 0; t < T_TILE; ++t) accP[t] = acc[t];

            c0 = c1; c1 = c2; c2 = cn;
        }
        // final reduction (si = 63)
        {
            float r0 = accP[0] + __shfl_xor_sync(0xffffffffu, accP[0], 16);
            float r1 = accP[1] + __shfl_xor_sync(0xffffffffu, accP[1], 16);
            float r2 = accP[2] + __shfl_xor_sync(0xffffffffu, accP[2], 16);
            float r3 = accP[3] + __shfl_xor_sync(0xffffffffu, accP[3], 16);
            float m01 = (lane & 16) ? r1 : r0;
            float m23 = (lane & 16) ? r3 : r2;
            m01 += __shfl_xor_sync(0xffffffffu, m01, 8);
            m23 += __shfl_xor_sync(0xffffffffu, m23, 8);
            float qv = (lane & 8) ? m23 : m01;
            qv += __shfl_xor_sync(0xffffffffu, qv, 4);
            qv += __shfl_xor_sync(0xffffffffu, qv, 2);
            qv += __shfl_xor_sync(0xffffffffu, qv, 1);
            if ((lane & 7) == 0) {
                int t = ((lane >> 4) & 1) + (((lane >> 3) & 1) << 1);
                lg[q][t][sg * 64 + 63] = qv;
            }
        }
    }
    __syncthreads();

    // ---- softmax: warps 0..3, row t = wid ----
    if (wid < T_TILE) {
        const float vb = v_b[0];
        const int t = wid;
        float e[8];
        float m = -1e30f;
#pragma unroll
        for (int k = 0; k < 8; ++k) {
            int i = k * 32 + lane;
            e[k] = lg[0][t][i] + lg[1][t][i] + lg[2][t][i] + lg[3][t][i] + vb;
            m = fmaxf(m, e[k]);
        }
#pragma unroll
        for (int o = 16; o; o >>= 1) m = fmaxf(m, __shfl_xor_sync(0xffffffffu, m, o));
        float ssum = 0.f;
#pragma unroll
        for (int k = 0; k < 8; ++k) {
            e[k] = __expf(e[k] - m);
            ssum += e[k];
        }
#pragma unroll
        for (int o = 16; o; o >>= 1) ssum += __shfl_xor_sync(0xffffffffu, ssum, o);
        const float inv = 1.0f / ssum;
        float* oa = out_attn + ((size_t)b * T_DIM + t0 + t) * S_DIM;
#pragma unroll
        for (int k = 0; k < 8; ++k)
            oa[k * 32 + lane] = e[k] * inv;
    }
}

// ---------------------------------------------------------------------------
// Kernel 3: weighted = attn @ values. grid=(B, 2, T/8)=256 blocks, 256 thr.
// ---------------------------------------------------------------------------
__global__ __launch_bounds__(256) void av_kernel(
    const float* __restrict__ values,    // (B,S,D)
    const float* __restrict__ attn,      // (B*T, S) normalized
    float* __restrict__ out_w)           // (T,B,D)
{
    __shared__ float p_s[T_AV][S_DIM];   // 8 KB

    const int b   = blockIdx.x;
    const int dh  = blockIdx.y;
    const int t0  = blockIdx.z * T_AV;
    const int tid = threadIdx.x;

    {
        const float4* ap = (const float4*)(attn + ((size_t)b * T_DIM + t0) * S_DIM);
        float4* ps4 = (float4*)p_s;
        for (int i = tid; i < T_AV * S_DIM / 4; i += 256) ps4[i] = ap[i];
    }
    __syncthreads();

    const int d = dh * 256 + tid;
    const float* vp = values + (size_t)b * S_DIM * D_DIM + d;

    float w[T_AV];
#pragma unroll
    for (int t = 0; t < T_AV; ++t) w[t] = 0.f;

    float v0 = vp[0 * D_DIM];
    float v1 = vp[1 * D_DIM];
    float v2 = vp[2 * D_DIM];
    float v3 = vp[3 * D_DIM];

    for (int s = 0; s < S_DIM; s += 4) {
        float n0, n1, n2, n3;
        if (s + 4 < S_DIM) {
            n0 = vp[(size_t)(s + 4) * D_DIM];
            n1 = vp[(size_t)(s + 5) * D_DIM];
            n2 = vp[(size_t)(s + 6) * D_DIM];
            n3 = vp[(size_t)(s + 7) * D_DIM];
        }
#pragma unroll
        for (int t = 0; t < T_AV; ++t) {
            float4 p = *(const float4*)&p_s[t][s];
            w[t] += p.x * v0 + p.y * v1 + p.z * v2 + p.w * v3;
        }
        v0 = n0; v1 = n1; v2 = n2; v3 = n3;
    }

#pragma unroll
    for (int t = 0; t < T_AV; ++t)
        out_w[((size_t)(t0 + t) * B_DIM + b) * D_DIM + d] = w[t];
}

// ---------------------------------------------------------------------------
extern "C" void kernel_launch(void* const* d_in, const int* in_sizes, int n_in,
                              void* d_out, int out_size) {
    const float* input   = (const float*)d_in[0];
    const float* context = (const float*)d_in[1];
    const float* values  = (const float*)d_in[2];
    const float* W_comb  = (const float*)d_in[3];
    const float* b_comb  = (const float*)d_in[4];
    const float* v_w     = (const float*)d_in[5];
    const float* v_b     = (const float*)d_in[6];

    float* out_weighted = (float*)d_out;                                 // (T,B,D)
    float* out_attn     = (float*)d_out + (size_t)T_DIM * B_DIM * D_DIM; // (B*T,S)

    dim3 g1(D_DIM / 64, (T_DIM * B_DIM) / 64);           // (8,16)
    gemm_kernel<<<g1, 512>>>(input, W_comb, b_comb);

    dim3 g2(B_DIM, T_DIM / T_TILE);                      // (16,16) = 256 blocks
    logits_kernel<<<g2, 512>>>(context, v_w, v_b, out_attn);

    dim3 g3(B_DIM, 2, T_DIM / T_AV);                     // (16,2,8) = 256 blocks
    av_kernel<<<g3, 256>>>(values, out_attn, out_weighted);
}

// round 7
// speedup vs baseline: 1.0678x; 1.0678x over previous
#include <cuda_runtime.h>
#include <cuda_bf16.h>

#define T_DIM 64
#define B_DIM 16
#define S_DIM 256
#define D_DIM 512
#define T_TILE 4       // t-rows per logits block
#define T_AV   8       // t-rows per AV block

// scratch: h = input @ W_comb + b_comb, stored (B, T, D)
__device__ float g_h[B_DIM * T_DIM * D_DIM];
// scratch: raw (un-softmaxed) logits, (B*T, S)
__device__ float g_lg[B_DIM * T_DIM * S_DIM];

__device__ __forceinline__ float tanh_ap(float x) {
    float y;
    asm("tanh.approx.f32 %0, %1;" : "=f"(y) : "f"(x));
    return y;
}

// ---------------------------------------------------------------------------
// Kernel 1: h = input @ W + bias  (M=1024, N=512, K=512)
// 64x32 tile, 256 thr, 4x2 microtile, double-buffered, grid=256 -> 2 CTA/SM.
// ---------------------------------------------------------------------------
__global__ __launch_bounds__(256, 2) void gemm_kernel(
    const float* __restrict__ A,
    const float* __restrict__ W,
    const float* __restrict__ bias)
{
    __shared__ float As[2][64][33];   // rows padded (scalar access)
    __shared__ float Bs[2][32][36];   // 144B rows (16B-aligned: 144=9*16)

    const int tid = threadIdx.x;
    const int tx = tid & 15;          // col pair: cols tx*2, tx*2+1
    const int ty = tid >> 4;          // row quad: rows ty*4..ty*4+3
    const int m0 = blockIdx.y * 64;
    const int n0 = blockIdx.x * 32;

    // A tile 64x32 = 512 float4 -> 2 per thread
    const int ar0 = tid >> 3,         ac0 = (tid & 7) * 4;
    const int ar1 = (tid + 256) >> 3, ac1 = ((tid + 256) & 7) * 4;
    // B tile 32x32 = 256 float4 -> 1 per thread
    const int br = tid >> 3, bc = (tid & 7) * 4;

    float acc[4][2];
#pragma unroll
    for (int i = 0; i < 4; ++i) { acc[i][0] = 0.f; acc[i][1] = 0.f; }

    // prologue -> buffer 0
    {
        float4 a0 = *(const float4*)&A[(size_t)(m0 + ar0) * D_DIM + ac0];
        float4 a1 = *(const float4*)&A[(size_t)(m0 + ar1) * D_DIM + ac1];
        float4 b0 = *(const float4*)&W[(size_t)br * D_DIM + n0 + bc];
        As[0][ar0][ac0 + 0] = a0.x; As[0][ar0][ac0 + 1] = a0.y;
        As[0][ar0][ac0 + 2] = a0.z; As[0][ar0][ac0 + 3] = a0.w;
        As[0][ar1][ac1 + 0] = a1.x; As[0][ar1][ac1 + 1] = a1.y;
        As[0][ar1][ac1 + 2] = a1.z; As[0][ar1][ac1 + 3] = a1.w;
        *(float4*)&Bs[0][br][bc] = b0;
    }
    __syncthreads();

    int buf = 0;
    for (int k0 = 0; k0 < D_DIM; k0 += 32) {
        const bool has_next = (k0 + 32) < D_DIM;
        float4 a0, a1, b0;
        if (has_next) {
            const int kn = k0 + 32;
            a0 = *(const float4*)&A[(size_t)(m0 + ar0) * D_DIM + kn + ac0];
            a1 = *(const float4*)&A[(size_t)(m0 + ar1) * D_DIM + kn + ac1];
            b0 = *(const float4*)&W[(size_t)(kn + br) * D_DIM + n0 + bc];
        }

#pragma unroll
        for (int k = 0; k < 32; ++k) {
            float2 b2 = *(const float2*)&Bs[buf][k][tx * 2];
            float x0 = As[buf][ty * 4 + 0][k];
            float x1 = As[buf][ty * 4 + 1][k];
            float x2 = As[buf][ty * 4 + 2][k];
            float x3 = As[buf][ty * 4 + 3][k];
            acc[0][0] += x0 * b2.x; acc[0][1] += x0 * b2.y;
            acc[1][0] += x1 * b2.x; acc[1][1] += x1 * b2.y;
            acc[2][0] += x2 * b2.x; acc[2][1] += x2 * b2.y;
            acc[3][0] += x3 * b2.x; acc[3][1] += x3 * b2.y;
        }

        if (has_next) {
            const int nb = buf ^ 1;
            As[nb][ar0][ac0 + 0] = a0.x; As[nb][ar0][ac0 + 1] = a0.y;
            As[nb][ar0][ac0 + 2] = a0.z; As[nb][ar0][ac0 + 3] = a0.w;
            As[nb][ar1][ac1 + 0] = a1.x; As[nb][ar1][ac1 + 1] = a1.y;
            As[nb][ar1][ac1 + 2] = a1.z; As[nb][ar1][ac1 + 3] = a1.w;
            *(float4*)&Bs[nb][br][bc] = b0;
        }
        __syncthreads();
        buf ^= 1;
    }

    const float bi0 = bias[n0 + tx * 2];
    const float bi1 = bias[n0 + tx * 2 + 1];
#pragma unroll
    for (int i = 0; i < 4; ++i) {
        int m = m0 + ty * 4 + i;
        int bb = m & (B_DIM - 1);
        int tt = m >> 4;
        float* dst = &g_h[((size_t)bb * T_DIM + tt) * D_DIM + n0 + tx * 2];
        dst[0] = acc[i][0] + bi0;
        dst[1] = acc[i][1] + bi1;
    }
}

// ---------------------------------------------------------------------------
// Kernel 2: raw logits. grid=(B, T/4, 2)=512 blocks, 512 thr, 2 CTA/SM.
// Block covers 128 s-values (s-split keeps context traffic unchanged).
// Warp w: quarter q=w&3 (128-dim D slice), sg=w>>2 (32 s values).
// Writes SUM over quarters to g_lg (no softmax, no v_b -- cancels in softmax).
// ---------------------------------------------------------------------------
__global__ __launch_bounds__(512, 2) void logits_kernel(
    const float* __restrict__ context,   // (B,S,D)
    const float* __restrict__ v_w)       // (D)
{
    __shared__ float h_s[T_TILE * D_DIM];          // 8 KB
    __shared__ float lg[4][T_TILE][128];           // 8 KB (quarter-partials)

    const int b    = blockIdx.x;
    const int t0   = blockIdx.y * T_TILE;
    const int sh   = blockIdx.z;         // s half: [sh*128, sh*128+128)
    const int tid  = threadIdx.x;
    const int wid  = tid >> 5;
    const int lane = tid & 31;
    const int q    = wid & 3;
    const int sg   = wid >> 2;           // 0..3, 32 s each

    {
        const float4* hp = (const float4*)(g_h + ((size_t)b * T_DIM + t0) * D_DIM);
        float4* hs4 = (float4*)h_s;
        for (int i = tid; i < T_TILE * D_DIM / 4; i += 512) hs4[i] = hp[i];
    }
    __syncthreads();

    {
        const int dof = q * 32 + lane;
        const float4* h4 = (const float4*)h_s;
        float4 hh[T_TILE];
#pragma unroll
        for (int t = 0; t < T_TILE; ++t)
            hh[t] = h4[t * (D_DIM / 4) + dof];
        const float4 ww = ((const float4*)v_w)[dof];

        const float4* cbase = (const float4*)(context + (size_t)b * S_DIM * D_DIM)
                              + (size_t)(sh * 128 + sg * 32) * (D_DIM / 4) + dof;

        float4 c0 = cbase[0];
        float4 c1 = cbase[1 * (D_DIM / 4)];
        float4 c2 = cbase[2 * (D_DIM / 4)];

        float accP[T_TILE];

        for (int si = 0; si < 32; ++si) {
            int pf = si + 3 < 32 ? si + 3 : 31;
            float4 cn = cbase[(size_t)pf * (D_DIM / 4)];

            float acc[T_TILE];
#pragma unroll
            for (int t = 0; t < T_TILE; ++t) {
                float a;
                a  = ww.x * tanh_ap(hh[t].x + c0.x);
                a += ww.y * tanh_ap(hh[t].y + c0.y);
                a += ww.z * tanh_ap(hh[t].z + c0.z);
                a += ww.w * tanh_ap(hh[t].w + c0.w);
                acc[t] = a;
            }

            if (si > 0) {
                float r0 = accP[0] + __shfl_xor_sync(0xffffffffu, accP[0], 16);
                float r1 = accP[1] + __shfl_xor_sync(0xffffffffu, accP[1], 16);
                float r2 = accP[2] + __shfl_xor_sync(0xffffffffu, accP[2], 16);
                float r3 = accP[3] + __shfl_xor_sync(0xffffffffu, accP[3], 16);
                float m01 = (lane & 16) ? r1 : r0;
                float m23 = (lane & 16) ? r3 : r2;
                m01 += __shfl_xor_sync(0xffffffffu, m01, 8);
                m23 += __shfl_xor_sync(0xffffffffu, m23, 8);
                float qv = (lane & 8) ? m23 : m01;
                qv += __shfl_xor_sync(0xffffffffu, qv, 4);
                qv += __shfl_xor_sync(0xffffffffu, qv, 2);
                qv += __shfl_xor_sync(0xffffffffu, qv, 1);
                if ((lane & 7) == 0) {
                    int t = ((lane >> 4) & 1) + (((lane >> 3) & 1) << 1);
                    lg[q][t][sg * 32 + si - 1] = qv;
                }
            }
#pragma unroll
            for (int t = 0; t < T_TILE; ++t) accP[t] = acc[t];

            c0 = c1; c1 = c2; c2 = cn;
        }
        {
            float r0 = accP[0] + __shfl_xor_sync(0xffffffffu, accP[0], 16);
            float r1 = accP[1] + __shfl_xor_sync(0xffffffffu, accP[1], 16);
            float r2 = accP[2] + __shfl_xor_sync(0xffffffffu, accP[2], 16);
            float r3 = accP[3] + __shfl_xor_sync(0xffffffffu, accP[3], 16);
            float m01 = (lane & 16) ? r1 : r0;
            float m23 = (lane & 16) ? r3 : r2;
            m01 += __shfl_xor_sync(0xffffffffu, m01, 8);
            m23 += __shfl_xor_sync(0xffffffffu, m23, 8);
            float qv = (lane & 8) ? m23 : m01;
            qv += __shfl_xor_sync(0xffffffffu, qv, 4);
            qv += __shfl_xor_sync(0xffffffffu, qv, 2);
            qv += __shfl_xor_sync(0xffffffffu, qv, 1);
            if ((lane & 7) == 0) {
                int t = ((lane >> 4) & 1) + (((lane >> 3) & 1) << 1);
                lg[q][t][sg * 32 + 31] = qv;
            }
        }
    }
    __syncthreads();

    // combine quarters, write raw logits (512 values, 1 per thread, coalesced)
    {
        const int t  = tid >> 7;
        const int sl = tid & 127;
        float v = lg[0][t][sl] + lg[1][t][sl] + lg[2][t][sl] + lg[3][t][sl];
        g_lg[((size_t)b * T_DIM + t0 + t) * S_DIM + sh * 128 + sl] = v;
    }
}

// ---------------------------------------------------------------------------
// Kernel 3: softmax + AV. grid=(B, 2, T/8)=256 blocks, 256 thr (8 warps).
// Loads raw logits, softmax warp-per-row, dh==0 writes out_attn, then AV.
// ---------------------------------------------------------------------------
__global__ __launch_bounds__(256) void av_kernel(
    const float* __restrict__ values,    // (B,S,D)
    float* __restrict__ out_attn,        // (B*T, S)
    float* __restrict__ out_w)           // (T,B,D)
{
    __shared__ float p_s[T_AV][S_DIM];   // 8 KB

    const int b    = blockIdx.x;
    const int dh   = blockIdx.y;
    const int t0   = blockIdx.z * T_AV;
    const int tid  = threadIdx.x;
    const int wid  = tid >> 5;
    const int lane = tid & 31;

    {
        const float4* lp = (const float4*)(g_lg + ((size_t)b * T_DIM + t0) * S_DIM);
        float4* ps4 = (float4*)p_s;
        for (int i = tid; i < T_AV * S_DIM / 4; i += 256) ps4[i] = lp[i];
    }
    __syncthreads();

    // softmax: warp wid owns row t = wid
    {
        const int t = wid;
        float e[8];
        float m = -1e30f;
#pragma unroll
        for (int k = 0; k < 8; ++k) {
            e[k] = p_s[t][k * 32 + lane];
            m = fmaxf(m, e[k]);
        }
#pragma unroll
        for (int o = 16; o; o >>= 1) m = fmaxf(m, __shfl_xor_sync(0xffffffffu, m, o));
        float ssum = 0.f;
#pragma unroll
        for (int k = 0; k < 8; ++k) {
            e[k] = __expf(e[k] - m);
            ssum += e[k];
        }
#pragma unroll
        for (int o = 16; o; o >>= 1) ssum += __shfl_xor_sync(0xffffffffu, ssum, o);
        const float inv = 1.0f / ssum;
        float* oa = out_attn + ((size_t)b * T_DIM + t0 + t) * S_DIM;
#pragma unroll
        for (int k = 0; k < 8; ++k) {
            float p = e[k] * inv;
            p_s[t][k * 32 + lane] = p;
            if (dh == 0) oa[k * 32 + lane] = p;
        }
    }
    __syncthreads();

    const int d = dh * 256 + tid;
    const float* vp = values + (size_t)b * S_DIM * D_DIM + d;

    float w[T_AV];
#pragma unroll
    for (int t = 0; t < T_AV; ++t) w[t] = 0.f;

    float v0 = vp[0 * D_DIM];
    float v1 = vp[1 * D_DIM];
    float v2 = vp[2 * D_DIM];
    float v3 = vp[3 * D_DIM];

    for (int s = 0; s < S_DIM; s += 4) {
        float n0, n1, n2, n3;
        if (s + 4 < S_DIM) {
            n0 = vp[(size_t)(s + 4) * D_DIM];
            n1 = vp[(size_t)(s + 5) * D_DIM];
            n2 = vp[(size_t)(s + 6) * D_DIM];
            n3 = vp[(size_t)(s + 7) * D_DIM];
        }
#pragma unroll
        for (int t = 0; t < T_AV; ++t) {
            float4 p = *(const float4*)&p_s[t][s];
            w[t] += p.x * v0 + p.y * v1 + p.z * v2 + p.w * v3;
        }
        v0 = n0; v1 = n1; v2 = n2; v3 = n3;
    }

#pragma unroll
    for (int t = 0; t < T_AV; ++t)
        out_w[((size_t)(t0 + t) * B_DIM + b) * D_DIM + d] = w[t];
}

// ---------------------------------------------------------------------------
extern "C" void kernel_launch(void* const* d_in, const int* in_sizes, int n_in,
                              void* d_out, int out_size) {
    const float* input   = (const float*)d_in[0];
    const float* context = (const float*)d_in[1];
    const float* values  = (const float*)d_in[2];
    const float* W_comb  = (const float*)d_in[3];
    const float* b_comb  = (const float*)d_in[4];
    const float* v_w     = (const float*)d_in[5];

    float* out_weighted = (float*)d_out;                                 // (T,B,D)
    float* out_attn     = (float*)d_out + (size_t)T_DIM * B_DIM * D_DIM; // (B*T,S)

    dim3 g1(D_DIM / 32, (T_DIM * B_DIM) / 64);           // (16,16) = 256 blocks
    gemm_kernel<<<g1, 256>>>(input, W_comb, b_comb);

    dim3 g2(B_DIM, T_DIM / T_TILE, 2);                   // (16,16,2) = 512 blocks
    logits_kernel<<<g2, 512>>>(context, v_w);

    dim3 g3(B_DIM, 2, T_DIM / T_AV);                     // (16,2,8) = 256 blocks
    av_kernel<<<g3, 256>>>(values, out_attn, out_weighted);
}

// round 8
// speedup vs baseline: 1.1610x; 1.0873x over previous
#include <cuda_runtime.h>
#include <cuda_bf16.h>
#include <cuda_fp16.h>

#define T_DIM 64
#define B_DIM 16
#define S_DIM 256
#define D_DIM 512
#define T_TILE 4       // t-rows per logits block
#define T_AV   8       // t-rows per AV block

// scratch: h = input @ W_comb + b_comb, stored (B, T, D)
__device__ float g_h[B_DIM * T_DIM * D_DIM];

__device__ __forceinline__ __half2 tanh2_ap(__half2 x) {
    unsigned xi = *(unsigned*)&x;
    unsigned yi;
    asm("tanh.approx.f16x2 %0, %1;" : "=r"(yi) : "r"(xi));
    return *(__half2*)&yi;
}

// ---------------------------------------------------------------------------
// Kernel 1: h = input @ W + bias (M=1024,N=512,K=512). R5-proven version:
// 64x64 tile, 256 thr, 4x4 microtile, double-buffered SMEM.
// ---------------------------------------------------------------------------
__global__ __launch_bounds__(256, 2) void gemm_kernel(
    const float* __restrict__ A,
    const float* __restrict__ W,
    const float* __restrict__ bias)
{
    __shared__ float As[2][64][33];
    __shared__ float Bs[2][32][68];

    const int tid = threadIdx.x;
    const int tx = tid & 15;
    const int ty = tid >> 4;
    const int m0 = blockIdx.y * 64;
    const int n0 = blockIdx.x * 64;

    const int ar0 = tid >> 3,         ac0 = (tid & 7) * 4;
    const int ar1 = (tid + 256) >> 3, ac1 = ((tid + 256) & 7) * 4;
    const int br0 = tid >> 4,         bc0 = (tid & 15) * 4;
    const int br1 = (tid + 256) >> 4, bc1 = ((tid + 256) & 15) * 4;

    float acc[4][4];
#pragma unroll
    for (int i = 0; i < 4; ++i)
#pragma unroll
        for (int j = 0; j < 4; ++j) acc[i][j] = 0.f;

    {
        float4 a0 = *(const float4*)&A[(size_t)(m0 + ar0) * D_DIM + ac0];
        float4 a1 = *(const float4*)&A[(size_t)(m0 + ar1) * D_DIM + ac1];
        float4 b0 = *(const float4*)&W[(size_t)br0 * D_DIM + n0 + bc0];
        float4 b1 = *(const float4*)&W[(size_t)br1 * D_DIM + n0 + bc1];
        As[0][ar0][ac0 + 0] = a0.x; As[0][ar0][ac0 + 1] = a0.y;
        As[0][ar0][ac0 + 2] = a0.z; As[0][ar0][ac0 + 3] = a0.w;
        As[0][ar1][ac1 + 0] = a1.x; As[0][ar1][ac1 + 1] = a1.y;
        As[0][ar1][ac1 + 2] = a1.z; As[0][ar1][ac1 + 3] = a1.w;
        *(float4*)&Bs[0][br0][bc0] = b0;
        *(float4*)&Bs[0][br1][bc1] = b1;
    }
    __syncthreads();

    int buf = 0;
    for (int k0 = 0; k0 < D_DIM; k0 += 32) {
        const bool has_next = (k0 + 32) < D_DIM;
        float4 a0, a1, b0, b1;
        if (has_next) {
            const int kn = k0 + 32;
            a0 = *(const float4*)&A[(size_t)(m0 + ar0) * D_DIM + kn + ac0];
            a1 = *(const float4*)&A[(size_t)(m0 + ar1) * D_DIM + kn + ac1];
            b0 = *(const float4*)&W[(size_t)(kn + br0) * D_DIM + n0 + bc0];
            b1 = *(const float4*)&W[(size_t)(kn + br1) * D_DIM + n0 + bc1];
        }

#pragma unroll
        for (int k = 0; k < 32; ++k) {
            float4 b4 = *(const float4*)&Bs[buf][k][tx * 4];
            float x0 = As[buf][ty * 4 + 0][k];
            float x1 = As[buf][ty * 4 + 1][k];
            float x2 = As[buf][ty * 4 + 2][k];
            float x3 = As[buf][ty * 4 + 3][k];
            acc[0][0] += x0 * b4.x; acc[0][1] += x0 * b4.y; acc[0][2] += x0 * b4.z; acc[0][3] += x0 * b4.w;
            acc[1][0] += x1 * b4.x; acc[1][1] += x1 * b4.y; acc[1][2] += x1 * b4.z; acc[1][3] += x1 * b4.w;
            acc[2][0] += x2 * b4.x; acc[2][1] += x2 * b4.y; acc[2][2] += x2 * b4.z; acc[2][3] += x2 * b4.w;
            acc[3][0] += x3 * b4.x; acc[3][1] += x3 * b4.y; acc[3][2] += x3 * b4.z; acc[3][3] += x3 * b4.w;
        }

        if (has_next) {
            const int nb = buf ^ 1;
            As[nb][ar0][ac0 + 0] = a0.x; As[nb][ar0][ac0 + 1] = a0.y;
            As[nb][ar0][ac0 + 2] = a0.z; As[nb][ar0][ac0 + 3] = a0.w;
            As[nb][ar1][ac1 + 0] = a1.x; As[nb][ar1][ac1 + 1] = a1.y;
            As[nb][ar1][ac1 + 2] = a1.z; As[nb][ar1][ac1 + 3] = a1.w;
            *(float4*)&Bs[nb][br0][bc0] = b0;
            *(float4*)&Bs[nb][br1][bc1] = b1;
        }
        __syncthreads();
        buf ^= 1;
    }

#pragma unroll
    for (int i = 0; i < 4; ++i) {
        int m = m0 + ty * 4 + i;
        int bb = m & (B_DIM - 1);
        int tt = m >> 4;
        float* dst = &g_h[((size_t)bb * T_DIM + tt) * D_DIM + n0 + tx * 4];
#pragma unroll
        for (int j = 0; j < 4; ++j)
            dst[j] = acc[i][j] + bias[n0 + tx * 4 + j];
    }
}

// ---------------------------------------------------------------------------
// Kernel 2: logits + softmax, fp16 tanh path.
// grid=(B, T/4)=256 blocks, 512 thr, 2 CTA/SM.
// Warp w: quarter q=w&3 (128-dim D slice, 4 dims/lane), sg=w>>2 (64 s).
// Per si: load c float4 -> 2 half2; per t: 2 HADD2 + 2 tanh.f16x2 + 2 HMUL2
// + 1 HADD2 pair-sum -> fp32 -> merged-butterfly lane reduction.
// ---------------------------------------------------------------------------
__global__ __launch_bounds__(512, 2) void logits_kernel(
    const float* __restrict__ context,   // (B,S,D)
    const float* __restrict__ v_w,       // (D)
    float* __restrict__ out_attn)        // (B*T, S) -> normalized probs
{
    __shared__ float h_s[T_TILE * D_DIM];          // 8 KB
    __shared__ float lg[4][T_TILE][S_DIM];         // 16 KB (quarter-partials)

    const int b    = blockIdx.x;
    const int t0   = blockIdx.y * T_TILE;
    const int tid  = threadIdx.x;
    const int wid  = tid >> 5;
    const int lane = tid & 31;
    const int q    = wid & 3;
    const int sg   = wid >> 2;

    {
        const float4* hp = (const float4*)(g_h + ((size_t)b * T_DIM + t0) * D_DIM);
        float4* hs4 = (float4*)h_s;
        for (int i = tid; i < T_TILE * D_DIM / 4; i += 512) hs4[i] = hp[i];
    }
    __syncthreads();

    // ---- logits ----
    {
        const int dof = q * 32 + lane;       // float4 idx within D row
        const float4* h4 = (const float4*)h_s;
        __half2 hh[T_TILE][2];
#pragma unroll
        for (int t = 0; t < T_TILE; ++t) {
            float4 hf = h4[t * (D_DIM / 4) + dof];
            hh[t][0] = __floats2half2_rn(hf.x, hf.y);
            hh[t][1] = __floats2half2_rn(hf.z, hf.w);
        }
        float4 wf = ((const float4*)v_w)[dof];
        const __half2 ww0 = __floats2half2_rn(wf.x, wf.y);
        const __half2 ww1 = __floats2half2_rn(wf.z, wf.w);

        const float4* cbase = (const float4*)(context + (size_t)b * S_DIM * D_DIM)
                              + (size_t)(sg * 64) * (D_DIM / 4) + dof;

        float4 c0 = cbase[0];
        float4 c1 = cbase[1 * (D_DIM / 4)];

        for (int si = 0; si < 64; ++si) {
            int pf = si + 2 < 64 ? si + 2 : 63;
            float4 cn = cbase[(size_t)pf * (D_DIM / 4)];

            const __half2 ca = __floats2half2_rn(c0.x, c0.y);
            const __half2 cb = __floats2half2_rn(c0.z, c0.w);

            float acc[T_TILE];
#pragma unroll
            for (int t = 0; t < T_TILE; ++t) {
                __half2 x0 = __hadd2(hh[t][0], ca);
                __half2 x1 = __hadd2(hh[t][1], cb);
                __half2 p0 = __hmul2(tanh2_ap(x0), ww0);
                __half2 p1 = __hmul2(tanh2_ap(x1), ww1);
                float2 ps = __half22float2(__hadd2(p0, p1));
                acc[t] = ps.x + ps.y;
            }

            // merged butterfly: 9 shfl reduce all 4 accumulators
            float r0 = acc[0] + __shfl_xor_sync(0xffffffffu, acc[0], 16);
            float r1 = acc[1] + __shfl_xor_sync(0xffffffffu, acc[1], 16);
            float r2 = acc[2] + __shfl_xor_sync(0xffffffffu, acc[2], 16);
            float r3 = acc[3] + __shfl_xor_sync(0xffffffffu, acc[3], 16);
            float m01 = (lane & 16) ? r1 : r0;
            float m23 = (lane & 16) ? r3 : r2;
            m01 += __shfl_xor_sync(0xffffffffu, m01, 8);
            m23 += __shfl_xor_sync(0xffffffffu, m23, 8);
            float qv = (lane & 8) ? m23 : m01;
            qv += __shfl_xor_sync(0xffffffffu, qv, 4);
            qv += __shfl_xor_sync(0xffffffffu, qv, 2);
            qv += __shfl_xor_sync(0xffffffffu, qv, 1);
            if ((lane & 7) == 0) {
                int t = ((lane >> 4) & 1) + (((lane >> 3) & 1) << 1);
                lg[q][t][sg * 64 + si] = qv;
            }
            c0 = c1; c1 = cn;
        }
    }
    __syncthreads();

    // ---- softmax: warps 0..3, row t = wid (v_b omitted: cancels) ----
    if (wid < T_TILE) {
        const int t = wid;
        float e[8];
        float m = -1e30f;
#pragma unroll
        for (int k = 0; k < 8; ++k) {
            int i = k * 32 + lane;
            e[k] = lg[0][t][i] + lg[1][t][i] + lg[2][t][i] + lg[3][t][i];
            m = fmaxf(m, e[k]);
        }
#pragma unroll
        for (int o = 16; o; o >>= 1) m = fmaxf(m, __shfl_xor_sync(0xffffffffu, m, o));
        float ssum = 0.f;
#pragma unroll
        for (int k = 0; k < 8; ++k) {
            e[k] = __expf(e[k] - m);
            ssum += e[k];
        }
#pragma unroll
        for (int o = 16; o; o >>= 1) ssum += __shfl_xor_sync(0xffffffffu, ssum, o);
        const float inv = 1.0f / ssum;
        float* oa = out_attn + ((size_t)b * T_DIM + t0 + t) * S_DIM;
#pragma unroll
        for (int k = 0; k < 8; ++k)
            oa[k * 32 + lane] = e[k] * inv;
    }
}

// ---------------------------------------------------------------------------
// Kernel 3: weighted = attn @ values. grid=(B, 2, T/8)=256 blocks, 256 thr.
// ---------------------------------------------------------------------------
__global__ __launch_bounds__(256) void av_kernel(
    const float* __restrict__ values,    // (B,S,D)
    const float* __restrict__ attn,      // (B*T, S) normalized
    float* __restrict__ out_w)           // (T,B,D)
{
    __shared__ float p_s[T_AV][S_DIM];   // 8 KB

    const int b   = blockIdx.x;
    const int dh  = blockIdx.y;
    const int t0  = blockIdx.z * T_AV;
    const int tid = threadIdx.x;

    {
        const float4* ap = (const float4*)(attn + ((size_t)b * T_DIM + t0) * S_DIM);
        float4* ps4 = (float4*)p_s;
        for (int i = tid; i < T_AV * S_DIM / 4; i += 256) ps4[i] = ap[i];
    }
    __syncthreads();

    const int d = dh * 256 + tid;
    const float* vp = values + (size_t)b * S_DIM * D_DIM + d;

    float w[T_AV];
#pragma unroll
    for (int t = 0; t < T_AV; ++t) w[t] = 0.f;

    float v0 = vp[0 * D_DIM];
    float v1 = vp[1 * D_DIM];
    float v2 = vp[2 * D_DIM];
    float v3 = vp[3 * D_DIM];

    for (int s = 0; s < S_DIM; s += 4) {
        float n0, n1, n2, n3;
        if (s + 4 < S_DIM) {
            n0 = vp[(size_t)(s + 4) * D_DIM];
            n1 = vp[(size_t)(s + 5) * D_DIM];
            n2 = vp[(size_t)(s + 6) * D_DIM];
            n3 = vp[(size_t)(s + 7) * D_DIM];
        }
#pragma unroll
        for (int t = 0; t < T_AV; ++t) {
            float4 p = *(const float4*)&p_s[t][s];
            w[t] += p.x * v0 + p.y * v1 + p.z * v2 + p.w * v3;
        }
        v0 = n0; v1 = n1; v2 = n2; v3 = n3;
    }

#pragma unroll
    for (int t = 0; t < T_AV; ++t)
        out_w[((size_t)(t0 + t) * B_DIM + b) * D_DIM + d] = w[t];
}

// ---------------------------------------------------------------------------
extern "C" void kernel_launch(void* const* d_in, const int* in_sizes, int n_in,
                              void* d_out, int out_size) {
    const float* input   = (const float*)d_in[0];
    const float* context = (const float*)d_in[1];
    const float* values  = (const float*)d_in[2];
    const float* W_comb  = (const float*)d_in[3];
    const float* b_comb  = (const float*)d_in[4];
    const float* v_w     = (const float*)d_in[5];

    float* out_weighted = (float*)d_out;                                 // (T,B,D)
    float* out_attn     = (float*)d_out + (size_t)T_DIM * B_DIM * D_DIM; // (B*T,S)

    dim3 g1(D_DIM / 64, (T_DIM * B_DIM) / 64);           // (8,16)
    gemm_kernel<<<g1, 256>>>(input, W_comb, b_comb);

    dim3 g2(B_DIM, T_DIM / T_TILE);                      // (16,16) = 256 blocks
    logits_kernel<<<g2, 512>>>(context, v_w, out_attn);

    dim3 g3(B_DIM, 2, T_DIM / T_AV);                     // (16,2,8) = 256 blocks
    av_kernel<<<g3, 256>>>(values, out_attn, out_weighted);
}